// round 14
// baseline (speedup 1.0000x reference)
#include <cuda_runtime.h>
#include <cuda_bf16.h>
#include <cuda_fp16.h>
#include <math.h>
#include <stdint.h>

// Problem constants
#define ORIG 19986
#define NEWR 37964
#define FACT 1024
#define DIM  768
#define BSZ  4096
#define KNEG 5
#define NIDS (BSZ * (KNEG + 2))   // 28672 sampled ids
#define MAXROWS NIDS
#define LDE 20032                  // padded logit-row length (64*313)
#define LDB1 20096                 // A2^T rows padded to whole 128-tile (157*128)
#define LOGIT_SHIFT 256.0f
#define NCB1 157                   // GEMM1 col blocks
#define NRB1 (MAXROWS / 128)       // 224 row blocks
#define GRP1 8                     // L2 supertile group

// Scratch (device globals)
__device__ __nv_bfloat16 g_Ebf[(size_t)MAXROWS * LDE];   // exp(logit-256) bf16
__device__ float g_newc[(size_t)MAXROWS * DIM];          // compacted new embeddings
__device__ __half g_A1h[(size_t)MAXROWS * FACT];         // gathered fp16 A1 rows
__device__ __half g_A2th[(size_t)LDB1 * FACT];           // A2^T fp16 [n][k], pad zeroed
__device__ __nv_bfloat16 g_Wt[(size_t)DIM * LDE];        // W^T bf16 [n][k]
__device__ float g_rspart[(size_t)MAXROWS * NCB1];       // per-colblock rowsum partials
__device__ int   g_slot[NEWR];
__device__ int   g_rows[MAXROWS];
__device__ int   g_count;
__device__ float g_rowsum[MAXROWS];
__device__ float g_loss[BSZ];

// ---------------------------------------------------------------------------
// Helpers
// ---------------------------------------------------------------------------
__device__ __forceinline__ void cp16(uint32_t dst, const void* src)
{
    asm volatile("cp.async.cg.shared.global [%0], [%1], 16;"
                 :: "r"(dst), "l"(src));
}

__device__ __forceinline__ void ldsm_x4(uint32_t& r0, uint32_t& r1,
                                        uint32_t& r2, uint32_t& r3, uint32_t addr)
{
    asm volatile("ldmatrix.sync.aligned.m8n8.x4.shared.b16 {%0,%1,%2,%3}, [%4];"
                 : "=r"(r0), "=r"(r1), "=r"(r2), "=r"(r3) : "r"(addr));
}

__device__ __forceinline__ void mma_fp16(float c[4],
                                         uint32_t a0, uint32_t a1, uint32_t a2, uint32_t a3,
                                         uint32_t b0, uint32_t b1)
{
    asm volatile(
        "mma.sync.aligned.m16n8k16.row.col.f32.f16.f16.f32 "
        "{%0,%1,%2,%3}, {%4,%5,%6,%7}, {%8,%9}, {%0,%1,%2,%3};"
        : "+f"(c[0]), "+f"(c[1]), "+f"(c[2]), "+f"(c[3])
        : "r"(a0), "r"(a1), "r"(a2), "r"(a3), "r"(b0), "r"(b1));
}

__device__ __forceinline__ void mma_bf16(float c[4],
                                         uint32_t a0, uint32_t a1, uint32_t a2, uint32_t a3,
                                         uint32_t b0, uint32_t b1)
{
    asm volatile(
        "mma.sync.aligned.m16n8k16.row.col.f32.bf16.bf16.f32 "
        "{%0,%1,%2,%3}, {%4,%5,%6,%7}, {%8,%9}, {%0,%1,%2,%3};"
        : "+f"(c[0]), "+f"(c[1]), "+f"(c[2]), "+f"(c[3])
        : "r"(a0), "r"(a1), "r"(a2), "r"(a3), "r"(b0), "r"(b1));
}

// ---------------------------------------------------------------------------
// Compaction
// ---------------------------------------------------------------------------
__global__ void reset_kernel()
{
    int i = blockIdx.x * blockDim.x + threadIdx.x;
    if (i < NEWR) g_slot[i] = -1;
    if (i == 0) g_count = 0;
}

__global__ void mark_kernel(const int* __restrict__ in_ids,
                            const int* __restrict__ pos_ids,
                            const int* __restrict__ neg_ids)
{
    int t = blockIdx.x * blockDim.x + threadIdx.x;
    if (t >= NIDS) return;
    int id;
    if (t < BSZ)          id = in_ids[t];
    else if (t < 2 * BSZ) id = pos_ids[t - BSZ];
    else                  id = neg_ids[t - 2 * BSZ];
    if (id >= ORIG) g_slot[id - ORIG] = -2;
}

__global__ void compact_kernel()
{
    int r = blockIdx.x * blockDim.x + threadIdx.x;
    if (r >= NEWR) return;
    if (g_slot[r] == -2) {
        int s = atomicAdd(&g_count, 1);
        g_slot[r] = s;
        g_rows[s] = r;
    }
}

// ---------------------------------------------------------------------------
// Operand prep
// ---------------------------------------------------------------------------
__global__ void prep_a1_kernel(const float* __restrict__ A1)
{
    int i = blockIdx.x * blockDim.x + threadIdx.x;   // over MAXROWS * 256
    int s = i >> 8;
    if (s >= g_count) return;
    int k = (i & 255) * 4;
    const float4 v = *reinterpret_cast<const float4*>(
        &A1[(size_t)g_rows[s] * FACT + k]);
    __half2 h0 = __floats2half2_rn(v.x, v.y);
    __half2 h1 = __floats2half2_rn(v.z, v.w);
    *reinterpret_cast<__half2*>(&g_A1h[(size_t)s * FACT + k])     = h0;
    *reinterpret_cast<__half2*>(&g_A1h[(size_t)s * FACT + k + 2]) = h1;
}

// Transpose A2 [1024, ORIG] -> g_A2th [LDB1][1024] fp16, pad rows zero.
__global__ __launch_bounds__(256)
void prep_a2t_kernel(const float* __restrict__ A2)
{
    __shared__ float t[32][33];
    const int n0 = blockIdx.x * 32;
    const int k0 = blockIdx.y * 32;
    const int tx = threadIdx.x & 31, ty0 = threadIdx.x >> 5;

    #pragma unroll
    for (int i = 0; i < 4; i++) {
        int ty = ty0 + i * 8;
        int k = k0 + ty, n = n0 + tx;
        t[ty][tx] = (n < ORIG) ? A2[(size_t)k * ORIG + n] : 0.f;
    }
    __syncthreads();
    #pragma unroll
    for (int i = 0; i < 4; i++) {
        int ty = ty0 + i * 8;
        int n = n0 + ty, k = k0 + tx;
        g_A2th[(size_t)n * FACT + k] = __float2half_rn(t[tx][ty]);
    }
}

// Transpose W [ORIG, 768] -> g_Wt [768][LDE] bf16, pad rows zero.
__global__ __launch_bounds__(256)
void prep_wt_kernel(const float* __restrict__ W)
{
    __shared__ float t[32][33];
    const int k0 = blockIdx.x * 32;      // up to LDE
    const int n0 = blockIdx.y * 32;      // up to 768
    const int tx = threadIdx.x & 31, ty0 = threadIdx.x >> 5;

    #pragma unroll
    for (int i = 0; i < 4; i++) {
        int ty = ty0 + i * 8;
        int k = k0 + ty, n = n0 + tx;
        t[ty][tx] = (k < ORIG) ? W[(size_t)k * DIM + n] : 0.f;
    }
    __syncthreads();
    #pragma unroll
    for (int i = 0; i < 4; i++) {
        int ty = ty0 + i * 8;
        int n = n0 + ty, k = k0 + tx;
        g_Wt[(size_t)n * LDE + k] = __float2bfloat16_rn(t[tx][ty]);
    }
}

// ---------------------------------------------------------------------------
// GEMM1 (fp16 mma + ldmatrix): logits = A1h[count,1024] @ A2th^T
// 128 threads, 2x2 warps, warp tile 64x64. BM=BN=128, BK=64, 3-stage ring.
// Fused exp epilogue + deterministic rowsum partials.
// ---------------------------------------------------------------------------
#define ASZ1 (128 * 36)            // words per operand tile (BK=64 halfs)
#define STG1 (2 * ASZ1)
#define SMEM1_BYTES (3 * STG1 * 4)   // 110592
#define CHB 2304                     // bytes per 16-row group in smem (16*36*4)

__global__ __launch_bounds__(128)
void gemm1_fp16()
{
    const int M = g_count;
    if (M == 0) return;

    const int lin = blockIdx.x;
    const int per_group = NCB1 * GRP1;
    const int grp = lin / per_group;
    const int rem = lin - grp * per_group;
    const int cb  = rem / GRP1;
    const int rb  = grp * GRP1 + (rem - cb * GRP1);
    const int row0 = rb * 128;
    if (row0 >= M) return;
    const int col0 = cb * 128;

    extern __shared__ __align__(16) uint32_t sm[];
    const uint32_t sb = (uint32_t)__cvta_generic_to_shared(sm);
    const int tid = threadIdx.x;

    // cp.async bases: 8 chunks/thread per operand, rows m0 + q*16.
    const int m0 = tid >> 3, c0 = tid & 7;
    const __half* aptr = g_A1h + (size_t)(row0 + m0) * FACT + c0 * 8;
    const __half* bptr = g_A2th + (size_t)(col0 + m0) * FACT + c0 * 8;
    const uint32_t adst = (uint32_t)((m0 * 36 + c0 * 4) * 4);
    const uint32_t bdst = (uint32_t)(ASZ1 * 4) + adst;

    auto load_stage = [&](int s, int k0) {
        uint32_t so = sb + (uint32_t)(s * STG1 * 4);
        #pragma unroll
        for (int q = 0; q < 8; q++)
            cp16(so + adst + q * CHB, aptr + k0 + (size_t)q * 16 * FACT);
        #pragma unroll
        for (int q = 0; q < 8; q++)
            cp16(so + bdst + q * CHB, bptr + k0 + (size_t)q * 16 * FACT);
    };

    const int wid = tid >> 5, lane = tid & 31;
    const int gid = lane >> 2, tig = lane & 3;
    const int warp_m = wid >> 1, warp_n = wid & 1;

    const uint32_t aoff = (uint32_t)(((warp_m * 64 + (lane & 15)) * 36
                                      + 4 * (lane >> 4)) * 4);
    const uint32_t boff = (uint32_t)((ASZ1 + (warp_n * 64 + (lane & 7)
                                      + ((lane >> 4) << 3)) * 36
                                      + ((lane >> 3) & 1) * 4) * 4);

    float acc[4][8][4];
    #pragma unroll
    for (int i = 0; i < 4; i++)
        #pragma unroll
        for (int j = 0; j < 8; j++)
            #pragma unroll
            for (int r = 0; r < 4; r++) acc[i][j][r] = 0.f;

    load_stage(0, 0);
    asm volatile("cp.async.commit_group;" ::: "memory");
    load_stage(1, 64);
    asm volatile("cp.async.commit_group;" ::: "memory");

    int sload = 2, scomp = 0;
    const int K_tiles = FACT / 64;   // 16
    for (int itk = 0; itk < K_tiles; itk++) {
        asm volatile("cp.async.wait_group 1;" ::: "memory");
        __syncthreads();

        int nx = itk + 2;
        if (nx < K_tiles) {
            load_stage(sload, nx * 64);
            sload = (sload == 2) ? 0 : sload + 1;
        }
        asm volatile("cp.async.commit_group;" ::: "memory");

        const uint32_t sbase = sb + (uint32_t)(scomp * STG1 * 4);
        scomp = (scomp == 2) ? 0 : scomp + 1;

        #pragma unroll
        for (int ks = 0; ks < 4; ks++) {
            const uint32_t kb = ks * 32;
            uint32_t af[4][4], bf[8][2];
            #pragma unroll
            for (int i = 0; i < 4; i++)
                ldsm_x4(af[i][0], af[i][1], af[i][2], af[i][3],
                        sbase + aoff + (uint32_t)(i * CHB) + kb);
            #pragma unroll
            for (int jj = 0; jj < 4; jj++)
                ldsm_x4(bf[2 * jj][0], bf[2 * jj][1],
                        bf[2 * jj + 1][0], bf[2 * jj + 1][1],
                        sbase + boff + (uint32_t)(jj * CHB) + kb);
            #pragma unroll
            for (int i = 0; i < 4; i++)
                #pragma unroll
                for (int j = 0; j < 8; j++)
                    mma_fp16(acc[i][j], af[i][0], af[i][1], af[i][2], af[i][3],
                             bf[j][0], bf[j][1]);
        }
    }
    __syncthreads();   // protect smem reuse by epilogue scratch

    // Fused epilogue: exp -> bf16 E + deterministic per-row partial sums
    float* rowred = reinterpret_cast<float*>(sm);   // 128 rows x 9 slots

    float rsum[4][2];
    #pragma unroll
    for (int i = 0; i < 4; i++) { rsum[i][0] = 0.f; rsum[i][1] = 0.f; }

    #pragma unroll
    for (int i = 0; i < 4; i++) {
        #pragma unroll
        for (int half = 0; half < 2; half++) {
            int gr = row0 + warp_m * 64 + i * 16 + gid + half * 8;
            if (gr >= M) continue;
            #pragma unroll
            for (int j = 0; j < 8; j++) {
                int gc = col0 + warp_n * 64 + j * 8 + 2 * tig;
                if (gc < ORIG) {
                    float e0 = __expf(acc[i][j][half * 2 + 0] - LOGIT_SHIFT);
                    float e1 = (gc + 1 < ORIG)
                             ? __expf(acc[i][j][half * 2 + 1] - LOGIT_SHIFT) : 0.f;
                    rsum[i][half] += e0 + e1;
                    *reinterpret_cast<__nv_bfloat162*>(
                        &g_Ebf[(size_t)gr * LDE + gc]) = __floats2bfloat162_rn(e0, e1);
                } else if (gc < LDE) {
                    *reinterpret_cast<uint32_t*>(&g_Ebf[(size_t)gr * LDE + gc]) = 0u;
                }
            }
        }
    }

    const int slot = warp_n * 4 + tig;
    #pragma unroll
    for (int i = 0; i < 4; i++)
        #pragma unroll
        for (int half = 0; half < 2; half++)
            rowred[(warp_m * 64 + i * 16 + half * 8 + gid) * 9 + slot] = rsum[i][half];
    __syncthreads();

    {
        int gr = row0 + tid;
        if (gr < M) {
            float s = 0.f;
            #pragma unroll
            for (int q = 0; q < 8; q++) s += rowred[tid * 9 + q];
            g_rspart[(size_t)gr * NCB1 + cb] = s;
        }
    }
}

// ---------------------------------------------------------------------------
// Rowsum reduce
// ---------------------------------------------------------------------------
__global__ __launch_bounds__(256)
void rowsum_reduce_kernel()
{
    const int row = blockIdx.x * 8 + (threadIdx.x >> 5);
    if (row >= g_count) return;
    const int lane = threadIdx.x & 31;
    float s = 0.f;
    for (int c = lane; c < NCB1; c += 32)
        s += g_rspart[(size_t)row * NCB1 + c];
    #pragma unroll
    for (int o = 16; o > 0; o >>= 1)
        s += __shfl_down_sync(0xFFFFFFFFu, s, o);
    if (lane == 0) g_rowsum[row] = s;
}

// ---------------------------------------------------------------------------
// GEMM2 (bf16 mma + ldmatrix): newc = (E[count,LDE] @ Wt^T) / rowsum
// 128 threads, 2x2 warps, warp tile 64x64. BM=BN=128, BK=64, 3-stage ring.
// ---------------------------------------------------------------------------
#define ASZ2 (128 * 36)
#define STG2 (2 * ASZ2)
#define SMEM2_BYTES (3 * STG2 * 4)   // 110592

__global__ __launch_bounds__(128)
void gemm2_tc()
{
    const int M = g_count;
    if (M == 0) return;
    const int row0 = blockIdx.y * 128;
    if (row0 >= M) return;
    const int col0 = blockIdx.x * 128;

    extern __shared__ __align__(16) uint32_t sm[];
    const uint32_t sb = (uint32_t)__cvta_generic_to_shared(sm);
    const int tid = threadIdx.x;

    const int m0 = tid >> 3, c0 = tid & 7;
    const __nv_bfloat16* aptr = g_Ebf + (size_t)(row0 + m0) * LDE + c0 * 8;
    const __nv_bfloat16* bptr = g_Wt + (size_t)(col0 + m0) * LDE + c0 * 8;
    const uint32_t adst = (uint32_t)((m0 * 36 + c0 * 4) * 4);
    const uint32_t bdst = (uint32_t)(ASZ2 * 4) + adst;

    auto load_stage = [&](int s, int k0) {
        uint32_t so = sb + (uint32_t)(s * STG2 * 4);
        #pragma unroll
        for (int q = 0; q < 8; q++)
            cp16(so + adst + q * CHB, aptr + k0 + (size_t)q * 16 * LDE);
        #pragma unroll
        for (int q = 0; q < 8; q++)
            cp16(so + bdst + q * CHB, bptr + k0 + (size_t)q * 16 * LDE);
    };

    const int wid = tid >> 5, lane = tid & 31;
    const int gid = lane >> 2, tig = lane & 3;
    const int warp_m = wid >> 1, warp_n = wid & 1;

    const uint32_t aoff = (uint32_t)(((warp_m * 64 + (lane & 15)) * 36
                                      + 4 * (lane >> 4)) * 4);
    const uint32_t boff = (uint32_t)((ASZ2 + (warp_n * 64 + (lane & 7)
                                      + ((lane >> 4) << 3)) * 36
                                      + ((lane >> 3) & 1) * 4) * 4);

    float acc[4][8][4];
    #pragma unroll
    for (int i = 0; i < 4; i++)
        #pragma unroll
        for (int j = 0; j < 8; j++)
            #pragma unroll
            for (int r = 0; r < 4; r++) acc[i][j][r] = 0.f;

    load_stage(0, 0);
    asm volatile("cp.async.commit_group;" ::: "memory");
    load_stage(1, 64);
    asm volatile("cp.async.commit_group;" ::: "memory");

    int sload = 2, scomp = 0;
    const int K_tiles = LDE / 64;   // 313
    for (int itk = 0; itk < K_tiles; itk++) {
        asm volatile("cp.async.wait_group 1;" ::: "memory");
        __syncthreads();

        int nx = itk + 2;
        if (nx < K_tiles) {
            load_stage(sload, nx * 64);
            sload = (sload == 2) ? 0 : sload + 1;
        }
        asm volatile("cp.async.commit_group;" ::: "memory");

        const uint32_t sbase = sb + (uint32_t)(scomp * STG2 * 4);
        scomp = (scomp == 2) ? 0 : scomp + 1;

        #pragma unroll
        for (int ks = 0; ks < 4; ks++) {
            const uint32_t kb = ks * 32;
            uint32_t af[4][4], bf[8][2];
            #pragma unroll
            for (int i = 0; i < 4; i++)
                ldsm_x4(af[i][0], af[i][1], af[i][2], af[i][3],
                        sbase + aoff + (uint32_t)(i * CHB) + kb);
            #pragma unroll
            for (int jj = 0; jj < 4; jj++)
                ldsm_x4(bf[2 * jj][0], bf[2 * jj][1],
                        bf[2 * jj + 1][0], bf[2 * jj + 1][1],
                        sbase + boff + (uint32_t)(jj * CHB) + kb);
            #pragma unroll
            for (int i = 0; i < 4; i++)
                #pragma unroll
                for (int j = 0; j < 8; j++)
                    mma_bf16(acc[i][j], af[i][0], af[i][1], af[i][2], af[i][3],
                             bf[j][0], bf[j][1]);
        }
    }

    #pragma unroll
    for (int i = 0; i < 4; i++) {
        #pragma unroll
        for (int half = 0; half < 2; half++) {
            int gr = row0 + warp_m * 64 + i * 16 + gid + half * 8;
            if (gr >= M) continue;
            float inv = 1.f / g_rowsum[gr];
            #pragma unroll
            for (int j = 0; j < 8; j++) {
                int gc = col0 + warp_n * 64 + j * 8 + 2 * tig;
                float2 v = make_float2(acc[i][j][half * 2 + 0] * inv,
                                       acc[i][j][half * 2 + 1] * inv);
                *reinterpret_cast<float2*>(&g_newc[(size_t)gr * DIM + gc]) = v;
            }
        }
    }
}

// ---------------------------------------------------------------------------
// Loss epilogue
// ---------------------------------------------------------------------------
__device__ __forceinline__ float softplus_f(float x)
{
    if (x > 20.f)  return x;
    if (x < -20.f) return expf(x);
    return log1pf(expf(x));
}

__global__ __launch_bounds__(256)
void loss_kernel(const float* __restrict__ W,
                 const int* __restrict__ in_ids, const int* __restrict__ pos_ids,
                 const int* __restrict__ neg_ids)
{
    __shared__ float redp[256];
    __shared__ float redn[256];
    const int b = blockIdx.x;

    auto rowptr = [&](int id) -> const float* {
        return (id < ORIG) ? (W + (size_t)id * DIM)
                           : (g_newc + (size_t)g_slot[id - ORIG] * DIM);
    };

    const float* ein = rowptr(in_ids[b]);
    const float* ep  = rowptr(pos_ids[b]);
    const float* en0 = rowptr(neg_ids[b * KNEG + 0]);
    const float* en1 = rowptr(neg_ids[b * KNEG + 1]);
    const float* en2 = rowptr(neg_ids[b * KNEG + 2]);
    const float* en3 = rowptr(neg_ids[b * KNEG + 3]);
    const float* en4 = rowptr(neg_ids[b * KNEG + 4]);

    float pd = 0.f, nd = 0.f;
    for (int d = threadIdx.x; d < DIM; d += 256) {
        float x = ein[d];
        pd += x * ep[d];
        nd += x * (en0[d] + en1[d] + en2[d] + en3[d] + en4[d]);
    }
    redp[threadIdx.x] = pd;
    redn[threadIdx.x] = nd;
    __syncthreads();
    #pragma unroll
    for (int s = 128; s > 0; s >>= 1) {
        if (threadIdx.x < s) {
            redp[threadIdx.x] += redp[threadIdx.x + s];
            redn[threadIdx.x] += redn[threadIdx.x + s];
        }
        __syncthreads();
    }
    if (threadIdx.x == 0)
        g_loss[b] = softplus_f(-redp[0]) + softplus_f(redn[0]);
}

__global__ __launch_bounds__(256)
void finalize_kernel(float* __restrict__ out)
{
    __shared__ float red[256];
    float s = 0.f;
    for (int i = threadIdx.x; i < BSZ; i += 256) s += g_loss[i];
    red[threadIdx.x] = s;
    __syncthreads();
    #pragma unroll
    for (int st = 128; st > 0; st >>= 1) {
        if (threadIdx.x < st) red[threadIdx.x] += red[threadIdx.x + st];
        __syncthreads();
    }
    if (threadIdx.x == 0) out[0] = red[0] / (float)BSZ;
}

// ---------------------------------------------------------------------------
// kernel_launch
// ---------------------------------------------------------------------------
extern "C" void kernel_launch(void* const* d_in, const int* in_sizes, int n_in,
                              void* d_out, int out_size)
{
    const float* W    = (const float*)d_in[0];
    const float* A1   = (const float*)d_in[1];
    const float* A2   = (const float*)d_in[2];
    const int* in_ids  = (const int*)d_in[3];
    const int* pos_ids = (const int*)d_in[4];
    const int* neg_ids = (const int*)d_in[5];
    float* out = (float*)d_out;

    cudaFuncSetAttribute(gemm1_fp16, cudaFuncAttributeMaxDynamicSharedMemorySize,
                         SMEM1_BYTES);
    cudaFuncSetAttribute(gemm2_tc, cudaFuncAttributeMaxDynamicSharedMemorySize,
                         SMEM2_BYTES);

    // 1. Compaction
    reset_kernel<<<(NEWR + 255) / 256, 256>>>();
    mark_kernel<<<(NIDS + 255) / 256, 256>>>(in_ids, pos_ids, neg_ids);
    compact_kernel<<<(NEWR + 255) / 256, 256>>>();

    // 2. Operand prep
    prep_a1_kernel<<<(MAXROWS * 256 + 255) / 256, 256>>>(A1);
    prep_a2t_kernel<<<dim3(LDB1 / 32, FACT / 32), 256>>>(A2);
    prep_wt_kernel<<<dim3(LDE / 32, DIM / 32), 256>>>(W);

    // 3. GEMM1 (fp16, 64x64 warp tiles, 128 threads) + fused exp + rowsums
    gemm1_fp16<<<NCB1 * NRB1, 128, SMEM1_BYTES>>>();

    // 4. Rowsum reduce
    rowsum_reduce_kernel<<<(MAXROWS + 7) / 8, 256>>>();

    // 5. GEMM2 (bf16, 64x64 warp tiles, 128 threads) with 1/rowsum epilogue
    {
        dim3 grid(DIM / 128, (MAXROWS + 127) / 128);
        gemm2_tc<<<grid, 128, SMEM2_BYTES>>>();
    }

    // 6. Loss + deterministic mean
    loss_kernel<<<BSZ, 256>>>(W, in_ids, pos_ids, neg_ids);
    finalize_kernel<<<1, 256>>>(out);
}

// round 15
// speedup vs baseline: 1.0689x; 1.0689x over previous
#include <cuda_runtime.h>
#include <cuda_bf16.h>
#include <cuda_fp16.h>
#include <math.h>
#include <stdint.h>

// Problem constants
#define ORIG 19986
#define NEWR 37964
#define FACT 1024
#define DIM  768
#define BSZ  4096
#define KNEG 5
#define NIDS (BSZ * (KNEG + 2))   // 28672 sampled ids
#define MAXROWS NIDS
#define LDE 20032                  // padded logit-row length (64*313)
#define LDB1 20096                 // A2^T rows padded to whole 128-tile (157*128)
#define LOGIT_SHIFT 256.0f
#define NCB1 157                   // GEMM1 col blocks
#define NRB1 (MAXROWS / 128)       // 224 row blocks
#define GRP1 8                     // L2 supertile group
#define NCB2 (DIM / 128)           // 6 GEMM2 col blocks
#define PERSIST2 304               // persistent CTAs for GEMM2

// Scratch (device globals)
__device__ __nv_bfloat16 g_Ebf[(size_t)MAXROWS * LDE];   // exp(logit-256) bf16
__device__ float g_newc[(size_t)MAXROWS * DIM];          // compacted new embeddings
__device__ __half g_A1h[(size_t)MAXROWS * FACT];         // gathered fp16 A1 rows
__device__ __half g_A2th[(size_t)LDB1 * FACT];           // A2^T fp16 [n][k], pad zeroed
__device__ __nv_bfloat16 g_Wt[(size_t)DIM * LDE];        // W^T bf16 [n][k]
__device__ float g_rspart[(size_t)MAXROWS * NCB1];       // per-colblock rowsum partials
__device__ int   g_slot[NEWR];
__device__ int   g_rows[MAXROWS];
__device__ int   g_count;
__device__ float g_rowsum[MAXROWS];
__device__ float g_loss[BSZ];

// ---------------------------------------------------------------------------
// Helpers
// ---------------------------------------------------------------------------
__device__ __forceinline__ void cp16(uint32_t dst, const void* src, int sz)
{
    asm volatile("cp.async.cg.shared.global [%0], [%1], 16, %2;"
                 :: "r"(dst), "l"(src), "r"(sz));
}

__device__ __forceinline__ void ldsm_x4(uint32_t& r0, uint32_t& r1,
                                        uint32_t& r2, uint32_t& r3, uint32_t addr)
{
    asm volatile("ldmatrix.sync.aligned.m8n8.x4.shared.b16 {%0,%1,%2,%3}, [%4];"
                 : "=r"(r0), "=r"(r1), "=r"(r2), "=r"(r3) : "r"(addr));
}

__device__ __forceinline__ void mma_fp16(float c[4],
                                         uint32_t a0, uint32_t a1, uint32_t a2, uint32_t a3,
                                         uint32_t b0, uint32_t b1)
{
    asm volatile(
        "mma.sync.aligned.m16n8k16.row.col.f32.f16.f16.f32 "
        "{%0,%1,%2,%3}, {%4,%5,%6,%7}, {%8,%9}, {%0,%1,%2,%3};"
        : "+f"(c[0]), "+f"(c[1]), "+f"(c[2]), "+f"(c[3])
        : "r"(a0), "r"(a1), "r"(a2), "r"(a3), "r"(b0), "r"(b1));
}

__device__ __forceinline__ void mma_bf16(float c[4],
                                         uint32_t a0, uint32_t a1, uint32_t a2, uint32_t a3,
                                         uint32_t b0, uint32_t b1)
{
    asm volatile(
        "mma.sync.aligned.m16n8k16.row.col.f32.bf16.bf16.f32 "
        "{%0,%1,%2,%3}, {%4,%5,%6,%7}, {%8,%9}, {%0,%1,%2,%3};"
        : "+f"(c[0]), "+f"(c[1]), "+f"(c[2]), "+f"(c[3])
        : "r"(a0), "r"(a1), "r"(a2), "r"(a3), "r"(b0), "r"(b1));
}

// ---------------------------------------------------------------------------
// Compaction
// ---------------------------------------------------------------------------
__global__ void reset_kernel()
{
    int i = blockIdx.x * blockDim.x + threadIdx.x;
    if (i < NEWR) g_slot[i] = -1;
    if (i == 0) g_count = 0;
}

__global__ void mark_kernel(const int* __restrict__ in_ids,
                            const int* __restrict__ pos_ids,
                            const int* __restrict__ neg_ids)
{
    int t = blockIdx.x * blockDim.x + threadIdx.x;
    if (t >= NIDS) return;
    int id;
    if (t < BSZ)          id = in_ids[t];
    else if (t < 2 * BSZ) id = pos_ids[t - BSZ];
    else                  id = neg_ids[t - 2 * BSZ];
    if (id >= ORIG) g_slot[id - ORIG] = -2;
}

__global__ void compact_kernel()
{
    int r = blockIdx.x * blockDim.x + threadIdx.x;
    if (r >= NEWR) return;
    if (g_slot[r] == -2) {
        int s = atomicAdd(&g_count, 1);
        g_slot[r] = s;
        g_rows[s] = r;
    }
}

// ---------------------------------------------------------------------------
// Operand prep
// ---------------------------------------------------------------------------
__global__ void prep_a1_kernel(const float* __restrict__ A1)
{
    int i = blockIdx.x * blockDim.x + threadIdx.x;   // over MAXROWS * 256
    int s = i >> 8;
    if (s >= g_count) return;
    int k = (i & 255) * 4;
    const float4 v = *reinterpret_cast<const float4*>(
        &A1[(size_t)g_rows[s] * FACT + k]);
    __half2 h0 = __floats2half2_rn(v.x, v.y);
    __half2 h1 = __floats2half2_rn(v.z, v.w);
    *reinterpret_cast<__half2*>(&g_A1h[(size_t)s * FACT + k])     = h0;
    *reinterpret_cast<__half2*>(&g_A1h[(size_t)s * FACT + k + 2]) = h1;
}

// Transpose A2 [1024, ORIG] -> g_A2th [LDB1][1024] fp16, pad rows zero.
__global__ __launch_bounds__(256)
void prep_a2t_kernel(const float* __restrict__ A2)
{
    __shared__ float t[32][33];
    const int n0 = blockIdx.x * 32;
    const int k0 = blockIdx.y * 32;
    const int tx = threadIdx.x & 31, ty0 = threadIdx.x >> 5;

    #pragma unroll
    for (int i = 0; i < 4; i++) {
        int ty = ty0 + i * 8;
        int k = k0 + ty, n = n0 + tx;
        t[ty][tx] = (n < ORIG) ? A2[(size_t)k * ORIG + n] : 0.f;
    }
    __syncthreads();
    #pragma unroll
    for (int i = 0; i < 4; i++) {
        int ty = ty0 + i * 8;
        int n = n0 + ty, k = k0 + tx;
        g_A2th[(size_t)n * FACT + k] = __float2half_rn(t[tx][ty]);
    }
}

// Transpose W [ORIG, 768] -> g_Wt [768][LDE] bf16, pad rows zero.
__global__ __launch_bounds__(256)
void prep_wt_kernel(const float* __restrict__ W)
{
    __shared__ float t[32][33];
    const int k0 = blockIdx.x * 32;      // up to LDE
    const int n0 = blockIdx.y * 32;      // up to 768
    const int tx = threadIdx.x & 31, ty0 = threadIdx.x >> 5;

    #pragma unroll
    for (int i = 0; i < 4; i++) {
        int ty = ty0 + i * 8;
        int k = k0 + ty, n = n0 + tx;
        t[ty][tx] = (k < ORIG) ? W[(size_t)k * DIM + n] : 0.f;
    }
    __syncthreads();
    #pragma unroll
    for (int i = 0; i < 4; i++) {
        int ty = ty0 + i * 8;
        int n = n0 + ty, k = k0 + tx;
        g_Wt[(size_t)n * LDE + k] = __float2bfloat16_rn(t[tx][ty]);
    }
}

// ---------------------------------------------------------------------------
// GEMM1 (fp16 mma + ldmatrix): logits = A1h[count,1024] @ A2th^T
// BM=BN=128, BK=64, 3-stage ring, ONE barrier/iter. (R13 configuration)
// ---------------------------------------------------------------------------
#define ASZ1 (128 * 36)            // words per operand tile (BK=64 halfs)
#define STG1 (2 * ASZ1)
#define SMEM1_BYTES (3 * STG1 * 4)   // 110592

__global__ __launch_bounds__(256)
void gemm1_fp16()
{
    const int M = g_count;
    if (M == 0) return;

    const int lin = blockIdx.x;
    const int per_group = NCB1 * GRP1;
    const int grp = lin / per_group;
    const int rem = lin - grp * per_group;
    const int cb  = rem / GRP1;
    const int rb  = grp * GRP1 + (rem - cb * GRP1);
    const int row0 = rb * 128;
    if (row0 >= M) return;
    const int col0 = cb * 128;

    extern __shared__ __align__(16) uint32_t sm[];
    const uint32_t sb = (uint32_t)__cvta_generic_to_shared(sm);
    const int tid = threadIdx.x;

    const __half* aptr[4]; int asz[4]; uint32_t adst[4];
    #pragma unroll
    for (int it = 0; it < 4; it++) {
        int idx = tid + it * 256;
        int m = idx >> 3, c = idx & 7;
        int gm = row0 + m;
        int cm = (gm < M) ? gm : 0;
        aptr[it] = g_A1h + (size_t)cm * FACT + c * 8;
        asz[it]  = (gm < M) ? 16 : 0;
        adst[it] = (uint32_t)((m * 36 + c * 4) * 4);
    }
    const __half* bptr[4]; uint32_t bdst[4];
    #pragma unroll
    for (int it = 0; it < 4; it++) {
        int idx = tid + it * 256;
        int n = idx >> 3, c = idx & 7;
        bptr[it] = g_A2th + (size_t)(col0 + n) * FACT + c * 8;
        bdst[it] = (uint32_t)((ASZ1 + n * 36 + c * 4) * 4);
    }

    auto load_stage = [&](int s, int k0) {
        uint32_t so = sb + (uint32_t)(s * STG1 * 4);
        #pragma unroll
        for (int it = 0; it < 4; it++)
            cp16(so + adst[it], aptr[it] + k0, asz[it]);
        #pragma unroll
        for (int it = 0; it < 4; it++)
            cp16(so + bdst[it], bptr[it] + k0, 16);
    };

    const int wid = tid >> 5, lane = tid & 31;
    const int gid = lane >> 2, tig = lane & 3;
    const int warp_m = wid >> 1, warp_n = wid & 1;

    const uint32_t aoff = (uint32_t)(((warp_m * 32 + (lane & 15)) * 36
                                      + 4 * (lane >> 4)) * 4);
    const uint32_t boff = (uint32_t)((ASZ1 + (warp_n * 64 + (lane & 7)
                                      + ((lane >> 4) << 3)) * 36
                                      + ((lane >> 3) & 1) * 4) * 4);

    float acc[2][8][4];
    #pragma unroll
    for (int i = 0; i < 2; i++)
        #pragma unroll
        for (int j = 0; j < 8; j++)
            #pragma unroll
            for (int r = 0; r < 4; r++) acc[i][j][r] = 0.f;

    load_stage(0, 0);
    asm volatile("cp.async.commit_group;" ::: "memory");
    load_stage(1, 64);
    asm volatile("cp.async.commit_group;" ::: "memory");

    int sload = 2, scomp = 0;
    const int K_tiles = FACT / 64;   // 16
    for (int itk = 0; itk < K_tiles; itk++) {
        asm volatile("cp.async.wait_group 1;" ::: "memory");
        __syncthreads();

        int nx = itk + 2;
        if (nx < K_tiles) {
            load_stage(sload, nx * 64);
            sload = (sload == 2) ? 0 : sload + 1;
        }
        asm volatile("cp.async.commit_group;" ::: "memory");

        const uint32_t sbase = sb + (uint32_t)(scomp * STG1 * 4);
        scomp = (scomp == 2) ? 0 : scomp + 1;

        #pragma unroll
        for (int ks = 0; ks < 4; ks++) {
            const uint32_t kb = ks * 32;
            uint32_t af[2][4], bf[8][2];
            ldsm_x4(af[0][0], af[0][1], af[0][2], af[0][3], sbase + aoff + kb);
            ldsm_x4(af[1][0], af[1][1], af[1][2], af[1][3],
                    sbase + aoff + 16 * 144 + kb);
            #pragma unroll
            for (int jj = 0; jj < 4; jj++)
                ldsm_x4(bf[2 * jj][0], bf[2 * jj][1],
                        bf[2 * jj + 1][0], bf[2 * jj + 1][1],
                        sbase + boff + (uint32_t)(jj * 16 * 144) + kb);
            #pragma unroll
            for (int i = 0; i < 2; i++)
                #pragma unroll
                for (int j = 0; j < 8; j++)
                    mma_fp16(acc[i][j], af[i][0], af[i][1], af[i][2], af[i][3],
                             bf[j][0], bf[j][1]);
        }
    }
    __syncthreads();   // protect smem reuse by epilogue scratch

    // Fused epilogue: exp -> bf16 E + deterministic per-row partial sums
    float* rowred = reinterpret_cast<float*>(sm);   // 128 rows x 9 slots

    float rsum[2][2] = {{0.f, 0.f}, {0.f, 0.f}};
    #pragma unroll
    for (int i = 0; i < 2; i++) {
        #pragma unroll
        for (int half = 0; half < 2; half++) {
            int gr = row0 + warp_m * 32 + i * 16 + gid + half * 8;
            if (gr >= M) continue;
            #pragma unroll
            for (int j = 0; j < 8; j++) {
                int gc = col0 + warp_n * 64 + j * 8 + 2 * tig;
                if (gc < ORIG) {
                    float e0 = __expf(acc[i][j][half * 2 + 0] - LOGIT_SHIFT);
                    float e1 = (gc + 1 < ORIG)
                             ? __expf(acc[i][j][half * 2 + 1] - LOGIT_SHIFT) : 0.f;
                    rsum[i][half] += e0 + e1;
                    *reinterpret_cast<__nv_bfloat162*>(
                        &g_Ebf[(size_t)gr * LDE + gc]) = __floats2bfloat162_rn(e0, e1);
                } else if (gc < LDE) {
                    *reinterpret_cast<uint32_t*>(&g_Ebf[(size_t)gr * LDE + gc]) = 0u;
                }
            }
        }
    }

    const int slot = warp_n * 4 + tig;
    #pragma unroll
    for (int i = 0; i < 2; i++)
        #pragma unroll
        for (int half = 0; half < 2; half++)
            rowred[(warp_m * 32 + i * 16 + half * 8 + gid) * 9 + slot] = rsum[i][half];
    __syncthreads();

    if (tid < 128) {
        int gr = row0 + tid;
        if (gr < M) {
            float s = 0.f;
            #pragma unroll
            for (int q = 0; q < 8; q++) s += rowred[tid * 9 + q];
            g_rspart[(size_t)gr * NCB1 + cb] = s;
        }
    }
}

// ---------------------------------------------------------------------------
// Rowsum reduce
// ---------------------------------------------------------------------------
__global__ __launch_bounds__(256)
void rowsum_reduce_kernel()
{
    const int row = blockIdx.x * 8 + (threadIdx.x >> 5);
    if (row >= g_count) return;
    const int lane = threadIdx.x & 31;
    float s = 0.f;
    for (int c = lane; c < NCB1; c += 32)
        s += g_rspart[(size_t)row * NCB1 + c];
    #pragma unroll
    for (int o = 16; o > 0; o >>= 1)
        s += __shfl_down_sync(0xFFFFFFFFu, s, o);
    if (lane == 0) g_rowsum[row] = s;
}

// ---------------------------------------------------------------------------
// GEMM2 (bf16 mma + ldmatrix): newc = (E[count,LDE] @ Wt^T) / rowsum
// BM=BN=128, BK=64, 3-stage ring, ONE barrier/iter.
// PERSISTENT: 1D grid of PERSIST2 CTAs loops over logical tiles (col-fast).
// ---------------------------------------------------------------------------
#define ASZ2 (128 * 36)            // words per operand tile (BK=64 halfs)
#define STG2 (2 * ASZ2)
#define SMEM2_BYTES (3 * STG2 * 4)   // 110592

__global__ __launch_bounds__(256)
void gemm2_tc()
{
    const int M = g_count;
    if (M == 0) return;
    const int n_tiles = ((M + 127) / 128) * NCB2;

    extern __shared__ __align__(16) uint32_t sm[];
    const uint32_t sb = (uint32_t)__cvta_generic_to_shared(sm);
    const int tid = threadIdx.x;

    const int wid = tid >> 5, lane = tid & 31;
    const int gid = lane >> 2, tig = lane & 3;
    const int warp_m = wid >> 1, warp_n = wid & 1;

    // Thread-constant pieces of the cp.async assignment
    const int am[4] = { (tid + 0) >> 3, (tid + 256) >> 3,
                        (tid + 512) >> 3, (tid + 768) >> 3 };
    const int ac[4] = { (tid + 0) & 7, (tid + 256) & 7,
                        (tid + 512) & 7, (tid + 768) & 7 };

    const uint32_t aoff = (uint32_t)(((warp_m * 32 + (lane & 15)) * 36
                                      + 4 * (lane >> 4)) * 4);
    const uint32_t boff = (uint32_t)((ASZ2 + (warp_n * 64 + (lane & 7)
                                      + ((lane >> 4) << 3)) * 36
                                      + ((lane >> 3) & 1) * 4) * 4);

    for (int t = blockIdx.x; t < n_tiles; t += gridDim.x) {
        const int row0 = (t / NCB2) * 128;
        const int col0 = (t % NCB2) * 128;

        const __nv_bfloat16* aptr[4]; int asz[4]; uint32_t adst[4];
        #pragma unroll
        for (int it = 0; it < 4; it++) {
            int gm = row0 + am[it];
            int cm = (gm < M) ? gm : 0;
            aptr[it] = g_Ebf + (size_t)cm * LDE + ac[it] * 8;
            asz[it]  = (gm < M) ? 16 : 0;
            adst[it] = (uint32_t)((am[it] * 36 + ac[it] * 4) * 4);
        }
        const __nv_bfloat16* bptr[4]; uint32_t bdst[4];
        #pragma unroll
        for (int it = 0; it < 4; it++) {
            bptr[it] = g_Wt + (size_t)(col0 + am[it]) * LDE + ac[it] * 8;
            bdst[it] = (uint32_t)((ASZ2 + am[it] * 36 + ac[it] * 4) * 4);
        }

        auto load_stage = [&](int s, int k0) {
            uint32_t so = sb + (uint32_t)(s * STG2 * 4);
            #pragma unroll
            for (int it = 0; it < 4; it++)
                cp16(so + adst[it], aptr[it] + k0, asz[it]);
            #pragma unroll
            for (int it = 0; it < 4; it++)
                cp16(so + bdst[it], bptr[it] + k0, 16);
        };

        float acc[2][8][4];
        #pragma unroll
        for (int i = 0; i < 2; i++)
            #pragma unroll
            for (int j = 0; j < 8; j++)
                #pragma unroll
                for (int r = 0; r < 4; r++) acc[i][j][r] = 0.f;

        __syncthreads();   // previous tile fully done with smem

        load_stage(0, 0);
        asm volatile("cp.async.commit_group;" ::: "memory");
        load_stage(1, 64);
        asm volatile("cp.async.commit_group;" ::: "memory");

        int sload = 2, scomp = 0;
        const int K_tiles = LDE / 64;   // 313
        for (int itk = 0; itk < K_tiles; itk++) {
            asm volatile("cp.async.wait_group 1;" ::: "memory");
            __syncthreads();

            int nx = itk + 2;
            if (nx < K_tiles) {
                load_stage(sload, nx * 64);
                sload = (sload == 2) ? 0 : sload + 1;
            }
            asm volatile("cp.async.commit_group;" ::: "memory");

            const uint32_t sbase = sb + (uint32_t)(scomp * STG2 * 4);
            scomp = (scomp == 2) ? 0 : scomp + 1;

            #pragma unroll
            for (int ks = 0; ks < 4; ks++) {
                const uint32_t kb = ks * 32;
                uint32_t af[2][4], bf[8][2];
                ldsm_x4(af[0][0], af[0][1], af[0][2], af[0][3], sbase + aoff + kb);
                ldsm_x4(af[1][0], af[1][1], af[1][2], af[1][3],
                        sbase + aoff + 16 * 144 + kb);
                #pragma unroll
                for (int jj = 0; jj < 4; jj++)
                    ldsm_x4(bf[2 * jj][0], bf[2 * jj][1],
                            bf[2 * jj + 1][0], bf[2 * jj + 1][1],
                            sbase + boff + (uint32_t)(jj * 16 * 144) + kb);
                #pragma unroll
                for (int i = 0; i < 2; i++)
                    #pragma unroll
                    for (int j = 0; j < 8; j++)
                        mma_bf16(acc[i][j], af[i][0], af[i][1], af[i][2], af[i][3],
                                 bf[j][0], bf[j][1]);
            }
        }

        #pragma unroll
        for (int i = 0; i < 2; i++) {
            #pragma unroll
            for (int half = 0; half < 2; half++) {
                int gr = row0 + warp_m * 32 + i * 16 + gid + half * 8;
                if (gr >= M) continue;
                float inv = 1.f / g_rowsum[gr];
                #pragma unroll
                for (int j = 0; j < 8; j++) {
                    int gc = col0 + warp_n * 64 + j * 8 + 2 * tig;
                    float2 v = make_float2(acc[i][j][half * 2 + 0] * inv,
                                           acc[i][j][half * 2 + 1] * inv);
                    *reinterpret_cast<float2*>(&g_newc[(size_t)gr * DIM + gc]) = v;
                }
            }
        }
    }
}

// ---------------------------------------------------------------------------
// Loss epilogue
// ---------------------------------------------------------------------------
__device__ __forceinline__ float softplus_f(float x)
{
    if (x > 20.f)  return x;
    if (x < -20.f) return expf(x);
    return log1pf(expf(x));
}

__global__ __launch_bounds__(256)
void loss_kernel(const float* __restrict__ W,
                 const int* __restrict__ in_ids, const int* __restrict__ pos_ids,
                 const int* __restrict__ neg_ids)
{
    __shared__ float redp[256];
    __shared__ float redn[256];
    const int b = blockIdx.x;

    auto rowptr = [&](int id) -> const float* {
        return (id < ORIG) ? (W + (size_t)id * DIM)
                           : (g_newc + (size_t)g_slot[id - ORIG] * DIM);
    };

    const float* ein = rowptr(in_ids[b]);
    const float* ep  = rowptr(pos_ids[b]);
    const float* en0 = rowptr(neg_ids[b * KNEG + 0]);
    const float* en1 = rowptr(neg_ids[b * KNEG + 1]);
    const float* en2 = rowptr(neg_ids[b * KNEG + 2]);
    const float* en3 = rowptr(neg_ids[b * KNEG + 3]);
    const float* en4 = rowptr(neg_ids[b * KNEG + 4]);

    float pd = 0.f, nd = 0.f;
    for (int d = threadIdx.x; d < DIM; d += 256) {
        float x = ein[d];
        pd += x * ep[d];
        nd += x * (en0[d] + en1[d] + en2[d] + en3[d] + en4[d]);
    }
    redp[threadIdx.x] = pd;
    redn[threadIdx.x] = nd;
    __syncthreads();
    #pragma unroll
    for (int s = 128; s > 0; s >>= 1) {
        if (threadIdx.x < s) {
            redp[threadIdx.x] += redp[threadIdx.x + s];
            redn[threadIdx.x] += redn[threadIdx.x + s];
        }
        __syncthreads();
    }
    if (threadIdx.x == 0)
        g_loss[b] = softplus_f(-redp[0]) + softplus_f(redn[0]);
}

__global__ __launch_bounds__(256)
void finalize_kernel(float* __restrict__ out)
{
    __shared__ float red[256];
    float s = 0.f;
    for (int i = threadIdx.x; i < BSZ; i += 256) s += g_loss[i];
    red[threadIdx.x] = s;
    __syncthreads();
    #pragma unroll
    for (int st = 128; st > 0; st >>= 1) {
        if (threadIdx.x < st) red[threadIdx.x] += red[threadIdx.x + st];
        __syncthreads();
    }
    if (threadIdx.x == 0) out[0] = red[0] / (float)BSZ;
}

// ---------------------------------------------------------------------------
// kernel_launch
// ---------------------------------------------------------------------------
extern "C" void kernel_launch(void* const* d_in, const int* in_sizes, int n_in,
                              void* d_out, int out_size)
{
    const float* W    = (const float*)d_in[0];
    const float* A1   = (const float*)d_in[1];
    const float* A2   = (const float*)d_in[2];
    const int* in_ids  = (const int*)d_in[3];
    const int* pos_ids = (const int*)d_in[4];
    const int* neg_ids = (const int*)d_in[5];
    float* out = (float*)d_out;

    cudaFuncSetAttribute(gemm1_fp16, cudaFuncAttributeMaxDynamicSharedMemorySize,
                         SMEM1_BYTES);
    cudaFuncSetAttribute(gemm2_tc, cudaFuncAttributeMaxDynamicSharedMemorySize,
                         SMEM2_BYTES);

    // 1. Compaction
    reset_kernel<<<(NEWR + 255) / 256, 256>>>();
    mark_kernel<<<(NIDS + 255) / 256, 256>>>(in_ids, pos_ids, neg_ids);
    compact_kernel<<<(NEWR + 255) / 256, 256>>>();

    // 2. Operand prep
    prep_a1_kernel<<<(MAXROWS * 256 + 255) / 256, 256>>>(A1);
    prep_a2t_kernel<<<dim3(LDB1 / 32, FACT / 32), 256>>>(A2);
    prep_wt_kernel<<<dim3(LDE / 32, DIM / 32), 256>>>(W);

    // 3. GEMM1 (fp16, BK=64, 256 threads) + fused exp + rowsum partials
    gemm1_fp16<<<NCB1 * NRB1, 256, SMEM1_BYTES>>>();

    // 4. Rowsum reduce
    rowsum_reduce_kernel<<<(MAXROWS + 7) / 8, 256>>>();

    // 5. GEMM2 (bf16, BK=64, persistent 1D grid) with 1/rowsum epilogue
    gemm2_tc<<<PERSIST2, 256, SMEM2_BYTES>>>();

    // 6. Loss + deterministic mean
    loss_kernel<<<BSZ, 256>>>(W, in_ids, pos_ids, neg_ids);
    finalize_kernel<<<1, 256>>>(out);
}

// round 17
// speedup vs baseline: 1.0782x; 1.0087x over previous
#include <cuda_runtime.h>
#include <cuda_bf16.h>
#include <cuda_fp16.h>
#include <math.h>
#include <stdint.h>

// Problem constants
#define ORIG 19986
#define NEWR 37964
#define FACT 1024
#define DIM  768
#define BSZ  4096
#define KNEG 5
#define NIDS (BSZ * (KNEG + 2))   // 28672 sampled ids
#define MAXROWS NIDS
#define LDE 20032                  // padded logit-row length (64*313)
#define LDB1 20096                 // A2^T rows padded to whole 128-tile (157*128)
#define LOGIT_SHIFT 256.0f
#define NCB1 157                   // GEMM1 col blocks
#define GRP1 8                     // L2 supertile group
#define NCB2 (DIM / 128)           // 6 GEMM2 col blocks
#define PERSIST 304                // persistent CTAs (2/SM x 152)

// Scratch (device globals)
__device__ __nv_bfloat16 g_Ebf[(size_t)MAXROWS * LDE];   // exp(logit-256) bf16
__device__ float g_newc[(size_t)MAXROWS * DIM];          // compacted new embeddings
__device__ __half g_A1h[(size_t)MAXROWS * FACT];         // gathered fp16 A1 rows
__device__ __half g_A2th[(size_t)LDB1 * FACT];           // A2^T fp16 [n][k], pad zeroed
__device__ __nv_bfloat16 g_Wt[(size_t)DIM * LDE];        // W^T bf16 [n][k]
__device__ float g_rspart[(size_t)MAXROWS * NCB1];       // per-colblock rowsum partials
__device__ int   g_slot[NEWR];
__device__ int   g_rows[MAXROWS];
__device__ int   g_count;
__device__ int   g_ticket1;
__device__ int   g_ticket2;
__device__ float g_rowsum[MAXROWS];
__device__ float g_loss[BSZ];

// ---------------------------------------------------------------------------
// Helpers
// ---------------------------------------------------------------------------
__device__ __forceinline__ void cp16(uint32_t dst, const void* src, int sz)
{
    asm volatile("cp.async.cg.shared.global [%0], [%1], 16, %2;"
                 :: "r"(dst), "l"(src), "r"(sz));
}

__device__ __forceinline__ void ldsm_x4(uint32_t& r0, uint32_t& r1,
                                        uint32_t& r2, uint32_t& r3, uint32_t addr)
{
    asm volatile("ldmatrix.sync.aligned.m8n8.x4.shared.b16 {%0,%1,%2,%3}, [%4];"
                 : "=r"(r0), "=r"(r1), "=r"(r2), "=r"(r3) : "r"(addr));
}

__device__ __forceinline__ void mma_fp16(float c[4],
                                         uint32_t a0, uint32_t a1, uint32_t a2, uint32_t a3,
                                         uint32_t b0, uint32_t b1)
{
    asm volatile(
        "mma.sync.aligned.m16n8k16.row.col.f32.f16.f16.f32 "
        "{%0,%1,%2,%3}, {%4,%5,%6,%7}, {%8,%9}, {%0,%1,%2,%3};"
        : "+f"(c[0]), "+f"(c[1]), "+f"(c[2]), "+f"(c[3])
        : "r"(a0), "r"(a1), "r"(a2), "r"(a3), "r"(b0), "r"(b1));
}

__device__ __forceinline__ void mma_bf16(float c[4],
                                         uint32_t a0, uint32_t a1, uint32_t a2, uint32_t a3,
                                         uint32_t b0, uint32_t b1)
{
    asm volatile(
        "mma.sync.aligned.m16n8k16.row.col.f32.bf16.bf16.f32 "
        "{%0,%1,%2,%3}, {%4,%5,%6,%7}, {%8,%9}, {%0,%1,%2,%3};"
        : "+f"(c[0]), "+f"(c[1]), "+f"(c[2]), "+f"(c[3])
        : "r"(a0), "r"(a1), "r"(a2), "r"(a3), "r"(b0), "r"(b1));
}

// ---------------------------------------------------------------------------
// Compaction
// ---------------------------------------------------------------------------
__global__ void reset_kernel()
{
    int i = blockIdx.x * blockDim.x + threadIdx.x;
    if (i < NEWR) g_slot[i] = -1;
    if (i == 0) { g_count = 0; g_ticket1 = 0; g_ticket2 = 0; }
}

__global__ void mark_kernel(const int* __restrict__ in_ids,
                            const int* __restrict__ pos_ids,
                            const int* __restrict__ neg_ids)
{
    int t = blockIdx.x * blockDim.x + threadIdx.x;
    if (t >= NIDS) return;
    int id;
    if (t < BSZ)          id = in_ids[t];
    else if (t < 2 * BSZ) id = pos_ids[t - BSZ];
    else                  id = neg_ids[t - 2 * BSZ];
    if (id >= ORIG) g_slot[id - ORIG] = -2;
}

__global__ void compact_kernel()
{
    int r = blockIdx.x * blockDim.x + threadIdx.x;
    if (r >= NEWR) return;
    if (g_slot[r] == -2) {
        int s = atomicAdd(&g_count, 1);
        g_slot[r] = s;
        g_rows[s] = r;
    }
}

// ---------------------------------------------------------------------------
// Operand prep
// ---------------------------------------------------------------------------
__global__ void prep_a1_kernel(const float* __restrict__ A1)
{
    int i = blockIdx.x * blockDim.x + threadIdx.x;   // over MAXROWS * 256
    int s = i >> 8;
    if (s >= g_count) return;
    int k = (i & 255) * 4;
    const float4 v = *reinterpret_cast<const float4*>(
        &A1[(size_t)g_rows[s] * FACT + k]);
    __half2 h0 = __floats2half2_rn(v.x, v.y);
    __half2 h1 = __floats2half2_rn(v.z, v.w);
    *reinterpret_cast<__half2*>(&g_A1h[(size_t)s * FACT + k])     = h0;
    *reinterpret_cast<__half2*>(&g_A1h[(size_t)s * FACT + k + 2]) = h1;
}

// Transpose A2 [1024, ORIG] -> g_A2th [LDB1][1024] fp16, pad rows zero.
__global__ __launch_bounds__(256)
void prep_a2t_kernel(const float* __restrict__ A2)
{
    __shared__ float t[32][33];
    const int n0 = blockIdx.x * 32;
    const int k0 = blockIdx.y * 32;
    const int tx = threadIdx.x & 31, ty0 = threadIdx.x >> 5;

    #pragma unroll
    for (int i = 0; i < 4; i++) {
        int ty = ty0 + i * 8;
        int k = k0 + ty, n = n0 + tx;
        t[ty][tx] = (n < ORIG) ? A2[(size_t)k * ORIG + n] : 0.f;
    }
    __syncthreads();
    #pragma unroll
    for (int i = 0; i < 4; i++) {
        int ty = ty0 + i * 8;
        int n = n0 + ty, k = k0 + tx;
        g_A2th[(size_t)n * FACT + k] = __float2half_rn(t[tx][ty]);
    }
}

// Transpose W [ORIG, 768] -> g_Wt [768][LDE] bf16, pad rows zero.
__global__ __launch_bounds__(256)
void prep_wt_kernel(const float* __restrict__ W)
{
    __shared__ float t[32][33];
    const int k0 = blockIdx.x * 32;      // up to LDE
    const int n0 = blockIdx.y * 32;      // up to 768
    const int tx = threadIdx.x & 31, ty0 = threadIdx.x >> 5;

    #pragma unroll
    for (int i = 0; i < 4; i++) {
        int ty = ty0 + i * 8;
        int k = k0 + ty, n = n0 + tx;
        t[ty][tx] = (k < ORIG) ? W[(size_t)k * DIM + n] : 0.f;
    }
    __syncthreads();
    #pragma unroll
    for (int i = 0; i < 4; i++) {
        int ty = ty0 + i * 8;
        int n = n0 + ty, k = k0 + tx;
        g_Wt[(size_t)n * LDE + k] = __float2bfloat16_rn(t[tx][ty]);
    }
}

// ---------------------------------------------------------------------------
// GEMM1 (fp16 mma + ldmatrix): logits = A1h[count,1024] @ A2th^T
// BM=BN=128, BK=64, 3-stage ring. PERSISTENT + ticket work stealing.
// Ticket index space padded to whole GRP1-groups so the swizzle is a
// bijection (R16 bug fix). Fused exp epilogue + rowsum partials.
// ---------------------------------------------------------------------------
#define ASZ1 (128 * 36)            // words per operand tile (BK=64 halfs)
#define STG1 (2 * ASZ1)
#define SMEM1_BYTES (3 * STG1 * 4)   // 110592

__global__ __launch_bounds__(256)
void gemm1_fp16()
{
    const int M = g_count;
    if (M == 0) return;
    const int nrb = (M + 127) / 128;
    const int nrb_pad = ((nrb + GRP1 - 1) / GRP1) * GRP1;   // whole groups
    const int n_tiles = nrb_pad * NCB1;

    extern __shared__ __align__(16) uint32_t sm[];
    __shared__ int s_t;
    const uint32_t sb = (uint32_t)__cvta_generic_to_shared(sm);
    const int tid = threadIdx.x;

    const int wid = tid >> 5, lane = tid & 31;
    const int gid = lane >> 2, tig = lane & 3;
    const int warp_m = wid >> 1, warp_n = wid & 1;

    const int am[4] = { (tid + 0) >> 3, (tid + 256) >> 3,
                        (tid + 512) >> 3, (tid + 768) >> 3 };
    const int ac[4] = { (tid + 0) & 7, (tid + 256) & 7,
                        (tid + 512) & 7, (tid + 768) & 7 };

    const uint32_t aoff = (uint32_t)(((warp_m * 32 + (lane & 15)) * 36
                                      + 4 * (lane >> 4)) * 4);
    const uint32_t boff = (uint32_t)((ASZ1 + (warp_n * 64 + (lane & 7)
                                      + ((lane >> 4) << 3)) * 36
                                      + ((lane >> 3) & 1) * 4) * 4);

    while (true) {
        if (tid == 0) s_t = atomicAdd(&g_ticket1, 1);
        __syncthreads();
        const int lin = s_t;
        if (lin >= n_tiles) break;

        // Supertile swizzle over the PADDED row space (bijection)
        const int per_group = NCB1 * GRP1;
        const int grp = lin / per_group;
        const int rem = lin - grp * per_group;
        const int cb  = rem / GRP1;
        const int rb  = grp * GRP1 + (rem - cb * GRP1);
        const int row0 = rb * 128;
        const int col0 = cb * 128;
        if (row0 >= M) { __syncthreads(); continue; }   // dead pad tile

        const __half* aptr[4]; int asz[4]; uint32_t adst[4];
        #pragma unroll
        for (int it = 0; it < 4; it++) {
            int gm = row0 + am[it];
            int cm = (gm < M) ? gm : 0;
            aptr[it] = g_A1h + (size_t)cm * FACT + ac[it] * 8;
            asz[it]  = (gm < M) ? 16 : 0;
            adst[it] = (uint32_t)((am[it] * 36 + ac[it] * 4) * 4);
        }
        const __half* bptr[4]; uint32_t bdst[4];
        #pragma unroll
        for (int it = 0; it < 4; it++) {
            bptr[it] = g_A2th + (size_t)(col0 + am[it]) * FACT + ac[it] * 8;
            bdst[it] = (uint32_t)((ASZ1 + am[it] * 36 + ac[it] * 4) * 4);
        }

        auto load_stage = [&](int s, int k0) {
            uint32_t so = sb + (uint32_t)(s * STG1 * 4);
            #pragma unroll
            for (int it = 0; it < 4; it++)
                cp16(so + adst[it], aptr[it] + k0, asz[it]);
            #pragma unroll
            for (int it = 0; it < 4; it++)
                cp16(so + bdst[it], bptr[it] + k0, 16);
        };

        float acc[2][8][4];
        #pragma unroll
        for (int i = 0; i < 2; i++)
            #pragma unroll
            for (int j = 0; j < 8; j++)
                #pragma unroll
                for (int r = 0; r < 4; r++) acc[i][j][r] = 0.f;

        load_stage(0, 0);
        asm volatile("cp.async.commit_group;" ::: "memory");
        load_stage(1, 64);
        asm volatile("cp.async.commit_group;" ::: "memory");

        int sload = 2, scomp = 0;
        const int K_tiles = FACT / 64;   // 16
        for (int itk = 0; itk < K_tiles; itk++) {
            asm volatile("cp.async.wait_group 1;" ::: "memory");
            __syncthreads();

            int nx = itk + 2;
            if (nx < K_tiles) {
                load_stage(sload, nx * 64);
                sload = (sload == 2) ? 0 : sload + 1;
            }
            asm volatile("cp.async.commit_group;" ::: "memory");

            const uint32_t sbase = sb + (uint32_t)(scomp * STG1 * 4);
            scomp = (scomp == 2) ? 0 : scomp + 1;

            #pragma unroll
            for (int ks = 0; ks < 4; ks++) {
                const uint32_t kb = ks * 32;
                uint32_t af[2][4], bf[8][2];
                ldsm_x4(af[0][0], af[0][1], af[0][2], af[0][3], sbase + aoff + kb);
                ldsm_x4(af[1][0], af[1][1], af[1][2], af[1][3],
                        sbase + aoff + 16 * 144 + kb);
                #pragma unroll
                for (int jj = 0; jj < 4; jj++)
                    ldsm_x4(bf[2 * jj][0], bf[2 * jj][1],
                            bf[2 * jj + 1][0], bf[2 * jj + 1][1],
                            sbase + boff + (uint32_t)(jj * 16 * 144) + kb);
                #pragma unroll
                for (int i = 0; i < 2; i++)
                    #pragma unroll
                    for (int j = 0; j < 8; j++)
                        mma_fp16(acc[i][j], af[i][0], af[i][1], af[i][2], af[i][3],
                                 bf[j][0], bf[j][1]);
            }
        }
        __syncthreads();   // mainloop smem done; reuse as epilogue scratch

        // Fused epilogue: exp -> bf16 E + deterministic per-row partial sums
        float* rowred = reinterpret_cast<float*>(sm);   // 128 rows x 9 slots

        float rsum[2][2] = {{0.f, 0.f}, {0.f, 0.f}};
        #pragma unroll
        for (int i = 0; i < 2; i++) {
            #pragma unroll
            for (int half = 0; half < 2; half++) {
                int gr = row0 + warp_m * 32 + i * 16 + gid + half * 8;
                if (gr >= M) continue;
                #pragma unroll
                for (int j = 0; j < 8; j++) {
                    int gc = col0 + warp_n * 64 + j * 8 + 2 * tig;
                    if (gc < ORIG) {
                        float e0 = __expf(acc[i][j][half * 2 + 0] - LOGIT_SHIFT);
                        float e1 = (gc + 1 < ORIG)
                                 ? __expf(acc[i][j][half * 2 + 1] - LOGIT_SHIFT) : 0.f;
                        rsum[i][half] += e0 + e1;
                        *reinterpret_cast<__nv_bfloat162*>(
                            &g_Ebf[(size_t)gr * LDE + gc]) = __floats2bfloat162_rn(e0, e1);
                    } else if (gc < LDE) {
                        *reinterpret_cast<uint32_t*>(&g_Ebf[(size_t)gr * LDE + gc]) = 0u;
                    }
                }
            }
        }

        const int slot = warp_n * 4 + tig;
        #pragma unroll
        for (int i = 0; i < 2; i++)
            #pragma unroll
            for (int half = 0; half < 2; half++)
                rowred[(warp_m * 32 + i * 16 + half * 8 + gid) * 9 + slot] = rsum[i][half];
        __syncthreads();

        if (tid < 128) {
            int gr = row0 + tid;
            if (gr < M) {
                float s = 0.f;
                #pragma unroll
                for (int q = 0; q < 8; q++) s += rowred[tid * 9 + q];
                g_rspart[(size_t)gr * NCB1 + cb] = s;
            }
        }
        __syncthreads();   // epilogue done before next tile's prologue/ticket
    }
}

// ---------------------------------------------------------------------------
// Rowsum reduce
// ---------------------------------------------------------------------------
__global__ __launch_bounds__(256)
void rowsum_reduce_kernel()
{
    const int row = blockIdx.x * 8 + (threadIdx.x >> 5);
    if (row >= g_count) return;
    const int lane = threadIdx.x & 31;
    float s = 0.f;
    for (int c = lane; c < NCB1; c += 32)
        s += g_rspart[(size_t)row * NCB1 + c];
    #pragma unroll
    for (int o = 16; o > 0; o >>= 1)
        s += __shfl_down_sync(0xFFFFFFFFu, s, o);
    if (lane == 0) g_rowsum[row] = s;
}

// ---------------------------------------------------------------------------
// GEMM2 (bf16 mma + ldmatrix): newc = (E[count,LDE] @ Wt^T) / rowsum
// BM=BN=128, BK=64, 3-stage ring. PERSISTENT + ticket work stealing.
// ---------------------------------------------------------------------------
#define ASZ2 (128 * 36)            // words per operand tile (BK=64 halfs)
#define STG2 (2 * ASZ2)
#define SMEM2_BYTES (3 * STG2 * 4)   // 110592

__global__ __launch_bounds__(256)
void gemm2_tc()
{
    const int M = g_count;
    if (M == 0) return;
    const int n_tiles = ((M + 127) / 128) * NCB2;

    extern __shared__ __align__(16) uint32_t sm[];
    __shared__ int s_t;
    const uint32_t sb = (uint32_t)__cvta_generic_to_shared(sm);
    const int tid = threadIdx.x;

    const int wid = tid >> 5, lane = tid & 31;
    const int gid = lane >> 2, tig = lane & 3;
    const int warp_m = wid >> 1, warp_n = wid & 1;

    const int am[4] = { (tid + 0) >> 3, (tid + 256) >> 3,
                        (tid + 512) >> 3, (tid + 768) >> 3 };
    const int ac[4] = { (tid + 0) & 7, (tid + 256) & 7,
                        (tid + 512) & 7, (tid + 768) & 7 };

    const uint32_t aoff = (uint32_t)(((warp_m * 32 + (lane & 15)) * 36
                                      + 4 * (lane >> 4)) * 4);
    const uint32_t boff = (uint32_t)((ASZ2 + (warp_n * 64 + (lane & 7)
                                      + ((lane >> 4) << 3)) * 36
                                      + ((lane >> 3) & 1) * 4) * 4);

    while (true) {
        if (tid == 0) s_t = atomicAdd(&g_ticket2, 1);
        __syncthreads();
        const int t = s_t;
        if (t >= n_tiles) break;

        const int row0 = (t / NCB2) * 128;
        const int col0 = (t % NCB2) * 128;

        const __nv_bfloat16* aptr[4]; int asz[4]; uint32_t adst[4];
        #pragma unroll
        for (int it = 0; it < 4; it++) {
            int gm = row0 + am[it];
            int cm = (gm < M) ? gm : 0;
            aptr[it] = g_Ebf + (size_t)cm * LDE + ac[it] * 8;
            asz[it]  = (gm < M) ? 16 : 0;
            adst[it] = (uint32_t)((am[it] * 36 + ac[it] * 4) * 4);
        }
        const __nv_bfloat16* bptr[4]; uint32_t bdst[4];
        #pragma unroll
        for (int it = 0; it < 4; it++) {
            bptr[it] = g_Wt + (size_t)(col0 + am[it]) * LDE + ac[it] * 8;
            bdst[it] = (uint32_t)((ASZ2 + am[it] * 36 + ac[it] * 4) * 4);
        }

        auto load_stage = [&](int s, int k0) {
            uint32_t so = sb + (uint32_t)(s * STG2 * 4);
            #pragma unroll
            for (int it = 0; it < 4; it++)
                cp16(so + adst[it], aptr[it] + k0, asz[it]);
            #pragma unroll
            for (int it = 0; it < 4; it++)
                cp16(so + bdst[it], bptr[it] + k0, 16);
        };

        float acc[2][8][4];
        #pragma unroll
        for (int i = 0; i < 2; i++)
            #pragma unroll
            for (int j = 0; j < 8; j++)
                #pragma unroll
                for (int r = 0; r < 4; r++) acc[i][j][r] = 0.f;

        load_stage(0, 0);
        asm volatile("cp.async.commit_group;" ::: "memory");
        load_stage(1, 64);
        asm volatile("cp.async.commit_group;" ::: "memory");

        int sload = 2, scomp = 0;
        const int K_tiles = LDE / 64;   // 313
        for (int itk = 0; itk < K_tiles; itk++) {
            asm volatile("cp.async.wait_group 1;" ::: "memory");
            __syncthreads();

            int nx = itk + 2;
            if (nx < K_tiles) {
                load_stage(sload, nx * 64);
                sload = (sload == 2) ? 0 : sload + 1;
            }
            asm volatile("cp.async.commit_group;" ::: "memory");

            const uint32_t sbase = sb + (uint32_t)(scomp * STG2 * 4);
            scomp = (scomp == 2) ? 0 : scomp + 1;

            #pragma unroll
            for (int ks = 0; ks < 4; ks++) {
                const uint32_t kb = ks * 32;
                uint32_t af[2][4], bf[8][2];
                ldsm_x4(af[0][0], af[0][1], af[0][2], af[0][3], sbase + aoff + kb);
                ldsm_x4(af[1][0], af[1][1], af[1][2], af[1][3],
                        sbase + aoff + 16 * 144 + kb);
                #pragma unroll
                for (int jj = 0; jj < 4; jj++)
                    ldsm_x4(bf[2 * jj][0], bf[2 * jj][1],
                            bf[2 * jj + 1][0], bf[2 * jj + 1][1],
                            sbase + boff + (uint32_t)(jj * 16 * 144) + kb);
                #pragma unroll
                for (int i = 0; i < 2; i++)
                    #pragma unroll
                    for (int j = 0; j < 8; j++)
                        mma_bf16(acc[i][j], af[i][0], af[i][1], af[i][2], af[i][3],
                                 bf[j][0], bf[j][1]);
            }
        }

        #pragma unroll
        for (int i = 0; i < 2; i++) {
            #pragma unroll
            for (int half = 0; half < 2; half++) {
                int gr = row0 + warp_m * 32 + i * 16 + gid + half * 8;
                if (gr >= M) continue;
                float inv = 1.f / g_rowsum[gr];
                #pragma unroll
                for (int j = 0; j < 8; j++) {
                    int gc = col0 + warp_n * 64 + j * 8 + 2 * tig;
                    float2 v = make_float2(acc[i][j][half * 2 + 0] * inv,
                                           acc[i][j][half * 2 + 1] * inv);
                    *reinterpret_cast<float2*>(&g_newc[(size_t)gr * DIM + gc]) = v;
                }
            }
        }
        __syncthreads();   // tile fully done with smem before next ticket
    }
}

// ---------------------------------------------------------------------------
// Loss epilogue
// ---------------------------------------------------------------------------
__device__ __forceinline__ float softplus_f(float x)
{
    if (x > 20.f)  return x;
    if (x < -20.f) return expf(x);
    return log1pf(expf(x));
}

__global__ __launch_bounds__(256)
void loss_kernel(const float* __restrict__ W,
                 const int* __restrict__ in_ids, const int* __restrict__ pos_ids,
                 const int* __restrict__ neg_ids)
{
    __shared__ float redp[256];
    __shared__ float redn[256];
    const int b = blockIdx.x;

    auto rowptr = [&](int id) -> const float* {
        return (id < ORIG) ? (W + (size_t)id * DIM)
                           : (g_newc + (size_t)g_slot[id - ORIG] * DIM);
    };

    const float* ein = rowptr(in_ids[b]);
    const float* ep  = rowptr(pos_ids[b]);
    const float* en0 = rowptr(neg_ids[b * KNEG + 0]);
    const float* en1 = rowptr(neg_ids[b * KNEG + 1]);
    const float* en2 = rowptr(neg_ids[b * KNEG + 2]);
    const float* en3 = rowptr(neg_ids[b * KNEG + 3]);
    const float* en4 = rowptr(neg_ids[b * KNEG + 4]);

    float pd = 0.f, nd = 0.f;
    for (int d = threadIdx.x; d < DIM; d += 256) {
        float x = ein[d];
        pd += x * ep[d];
        nd += x * (en0[d] + en1[d] + en2[d] + en3[d] + en4[d]);
    }
    redp[threadIdx.x] = pd;
    redn[threadIdx.x] = nd;
    __syncthreads();
    #pragma unroll
    for (int s = 128; s > 0; s >>= 1) {
        if (threadIdx.x < s) {
            redp[threadIdx.x] += redp[threadIdx.x + s];
            redn[threadIdx.x] += redn[threadIdx.x + s];
        }
        __syncthreads();
    }
    if (threadIdx.x == 0)
        g_loss[b] = softplus_f(-redp[0]) + softplus_f(redn[0]);
}

__global__ __launch_bounds__(256)
void finalize_kernel(float* __restrict__ out)
{
    __shared__ float red[256];
    float s = 0.f;
    for (int i = threadIdx.x; i < BSZ; i += 256) s += g_loss[i];
    red[threadIdx.x] = s;
    __syncthreads();
    #pragma unroll
    for (int st = 128; st > 0; st >>= 1) {
        if (threadIdx.x < st) red[threadIdx.x] += red[threadIdx.x + st];
        __syncthreads();
    }
    if (threadIdx.x == 0) out[0] = red[0] / (float)BSZ;
}

// ---------------------------------------------------------------------------
// kernel_launch
// ---------------------------------------------------------------------------
extern "C" void kernel_launch(void* const* d_in, const int* in_sizes, int n_in,
                              void* d_out, int out_size)
{
    const float* W    = (const float*)d_in[0];
    const float* A1   = (const float*)d_in[1];
    const float* A2   = (const float*)d_in[2];
    const int* in_ids  = (const int*)d_in[3];
    const int* pos_ids = (const int*)d_in[4];
    const int* neg_ids = (const int*)d_in[5];
    float* out = (float*)d_out;

    cudaFuncSetAttribute(gemm1_fp16, cudaFuncAttributeMaxDynamicSharedMemorySize,
                         SMEM1_BYTES);
    cudaFuncSetAttribute(gemm2_tc, cudaFuncAttributeMaxDynamicSharedMemorySize,
                         SMEM2_BYTES);

    // 1. Compaction (+ ticket reset)
    reset_kernel<<<(NEWR + 255) / 256, 256>>>();
    mark_kernel<<<(NIDS + 255) / 256, 256>>>(in_ids, pos_ids, neg_ids);
    compact_kernel<<<(NEWR + 255) / 256, 256>>>();

    // 2. Operand prep
    prep_a1_kernel<<<(MAXROWS * 256 + 255) / 256, 256>>>(A1);
    prep_a2t_kernel<<<dim3(LDB1 / 32, FACT / 32), 256>>>(A2);
    prep_wt_kernel<<<dim3(LDE / 32, DIM / 32), 256>>>(W);

    // 3. GEMM1 (persistent + ticket, padded index space) + exp + rowsums
    gemm1_fp16<<<PERSIST, 256, SMEM1_BYTES>>>();

    // 4. Rowsum reduce
    rowsum_reduce_kernel<<<(MAXROWS + 7) / 8, 256>>>();

    // 5. GEMM2 (persistent + ticket) with 1/rowsum epilogue
    gemm2_tc<<<PERSIST, 256, SMEM2_BYTES>>>();

    // 6. Loss + deterministic mean
    loss_kernel<<<BSZ, 256>>>(W, in_ids, pos_ids, neg_ids);
    finalize_kernel<<<1, 256>>>(out);
}